// round 11
// baseline (speedup 1.0000x reference)
#include <cuda_runtime.h>
#include <cuda_fp16.h>
#include <cstdint>

#define BB 128          // batch
#define PP 1200         // feature dim
#define NPB (BB * PP)   // 153600
#define MAXCH 32        // max p-chunks per iteration

// Static scratch (ping-pong everything to avoid same-launch read/write races)
__device__ float g_hA[NPB];               // h state buffer A
__device__ float g_hB[NPB];               // h state buffer B
__device__ float g_C0[NPB];               // frozen-contribution cache buffers
__device__ float g_C1[NPB];
__device__ float g_pA[MAXCH * NPB];       // partial sums ping
__device__ float g_pB[MAXCH * NPB];       // partial sums pong
// fp16 compact pack of M[b, p<720, q<480], layout [b][qblk(2)][p(720)][qin(240)]
// written by F2 while it streams those values anyway; read by F3 (all) and
// F4 (qblk 0, p<480). 88.5 MB.
__device__ __align__(16) __half g_pack[(size_t)BB * 2 * 720 * 240];

__device__ __forceinline__ float f_p(float x) {
    float t = fminf(fmaxf(x, -1.0f), 1.0f);
    return t > 0.0f ? t : 0.01f * t;
}

// streaming loads (.cs evict-first; M/pack are single-use per launch)
struct U64x2 { unsigned long long a, b; };
__device__ __forceinline__ U64x2 ldg_cs_128(const void* p) {
    U64x2 r;
    asm("ld.global.cs.v2.u64 {%0,%1}, [%2];" : "=l"(r.a), "=l"(r.b) : "l"(p));
    return r;
}
__device__ __forceinline__ unsigned long long ldg_cs_64(const void* p) {
    unsigned long long r;
    asm("ld.global.cs.u64 %0, [%1];" : "=l"(r) : "l"(p));
    return r;
}
__device__ __forceinline__ void stg_cs_64(void* p, unsigned long long v) {
    asm volatile("st.global.cs.u64 [%0], %1;" :: "l"(p), "l"(v) : "memory");
}

// Packed dual-fp32 FMA: acc = m * hp + acc   (Blackwell f32x2 pipe)
#define FMA2(acc, m, hp) \
    asm("fma.rn.f32x2 %0, %1, %2, %0;" : "+l"(acc) : "l"(m), "l"(hp))

// fp16x2 (as uint32) -> packed f32x2 (as ull)
__device__ __forceinline__ unsigned long long h2_to_f2(unsigned int h2) {
    __half2 hh = *reinterpret_cast<__half2*>(&h2);
    float2 f = __half22float2(hh);
    return *reinterpret_cast<unsigned long long*>(&f);
}

// ---------------------------------------------------------------------------
// mainloop: partial_out[ch][b][q0..q0+QPT-1] = sum_{p in chunk} hd[p]*M[b,p,q]
// QPT = q floats per thread (4 -> LDG.128/p, 2 -> LDG.64/p)
// EMIT: additionally write fp16 pack rows (F2 only; caller guarantees the
//       whole chunk is p<720 and q0<480).
// ---------------------------------------------------------------------------
template<int PC, int QPT, bool EMIT>
__device__ __forceinline__ void mainloopA(
    const float* __restrict__ M, const float2* hd, float* __restrict__ pout,
    int ch, int b, int q0)
{
    const char* base = (const char*)(M + (size_t)b * PP * PP
                                       + (size_t)(ch * PC) * PP + q0);
    if (QPT == 4) {
        __half* pk = nullptr;
        if (EMIT) {
            int qblk = q0 / 240, qin = q0 % 240;
            pk = g_pack + (((size_t)b * 2 + qblk) * 720 + ch * PC) * 240 + qin;
        }
        unsigned long long acc0 = 0, acc1 = 0;
        #pragma unroll 8
        for (int p = 0; p < PC; ++p) {
            unsigned long long hp = *reinterpret_cast<const unsigned long long*>(&hd[p]);
            U64x2 m = ldg_cs_128(base + (size_t)p * (PP * 4));
            FMA2(acc0, m.a, hp);
            FMA2(acc1, m.b, hp);
            if (EMIT) {
                float2 lo = *reinterpret_cast<float2*>(&m.a);
                float2 hi = *reinterpret_cast<float2*>(&m.b);
                __half2 hlo = __float22half2_rn(lo);
                __half2 hhi = __float22half2_rn(hi);
                unsigned long long v =
                    (unsigned long long)(*reinterpret_cast<unsigned*>(&hlo)) |
                    ((unsigned long long)(*reinterpret_cast<unsigned*>(&hhi)) << 32);
                stg_cs_64(pk + (size_t)p * 240, v);
            }
        }
        unsigned long long* out = reinterpret_cast<unsigned long long*>(
            pout + ((size_t)ch * BB + b) * PP + q0);
        out[0] = acc0;
        out[1] = acc1;
    } else {
        unsigned long long acc0 = 0;
        #pragma unroll 8
        for (int p = 0; p < PC; ++p) {
            unsigned long long hp = *reinterpret_cast<const unsigned long long*>(&hd[p]);
            unsigned long long m = ldg_cs_64(base + (size_t)p * (PP * 4));
            FMA2(acc0, m, hp);
        }
        *reinterpret_cast<unsigned long long*>(
            pout + ((size_t)ch * BB + b) * PP + q0) = acc0;
    }
}

// ---------------------------------------------------------------------------
// iter-0 phase A: h = f_p(query); partials(0) -> pA
// ---------------------------------------------------------------------------
template<int PC>
__global__ void phaseA0(const float* __restrict__ M, const float* __restrict__ query)
{
    const int ch = blockIdx.x, b = blockIdx.y, tid = threadIdx.x;
    __shared__ float2 hd[PC];
    if (tid < PC) {
        float v = f_p(query[b * PP + ch * PC + tid]);
        hd[tid] = make_float2(v, v);
    }
    __syncthreads();
    const int q0 = blockIdx.z * (blockDim.x * 4) + tid * 4;
    if (q0 >= PP) return;
    mainloopA<PC, 4, false>(M, hd, g_pA, ch, b, q0);
}

// ---------------------------------------------------------------------------
// fused kernels F1/F2 (fp32 M path; F2 additionally emits the fp16 pack):
//   prologue: h_t[window] = f_p(h_{t-1}*(0.8 + C_in + sum partials_in));
//             z==0 block persists h_t (q<QLO) or writes the just-frozen
//             output slice [QLO, window_end) to d_out; folds frozen chunks
//             into C_out.
//   mainloop: partials_t over q < n_on.
// ---------------------------------------------------------------------------
template<int PC, int QPT, int NCHP, int NACTP,
         bool READC, bool WRITEC, bool FIRSTW, bool IT0P, int QLO, bool EMIT>
__global__ void phaseF(const float* __restrict__ M,
                       const float* __restrict__ hin, float* __restrict__ hout,
                       const float* __restrict__ Cin, float* __restrict__ Cout,
                       const float* __restrict__ pin, float* __restrict__ pout,
                       float* __restrict__ outF, int n_on)
{
#if __CUDA_ARCH__ >= 900
    cudaGridDependencySynchronize();
#endif
    const int ch = blockIdx.x, b = blockIdx.y, tid = threadIdx.x;
    const int pbase = ch * PC;
    __shared__ float2 hd[PC];

    if (tid < PC) {
        const int q  = pbase + tid;
        const int gi = b * PP + q;
        float h = hin[gi];
        if (IT0P) h = f_p(h);

        float sa = 0.0f, sf = 0.0f;
        const float* pp = pin + (size_t)b * PP + q;
        #pragma unroll
        for (int s = 0; s < NCHP; ++s) {
            float v = pp[(size_t)s * NPB];
            if (s < NACTP) sa += v; else sf += v;
        }
        float c = READC ? Cin[gi] : 0.0f;
        float hnew = f_p(h * (0.8f + sa + sf + c));
        hd[tid] = make_float2(hnew, hnew);

        if (blockIdx.z == 0) {
            if (q >= QLO) {
                outF[gi] = hnew;                 // just-frozen final slice
            } else {
                hout[gi] = hnew;
                if (WRITEC) Cout[gi] = FIRSTW ? sf : (c + sf);
            }
        }
    }
    __syncthreads();

    const int q0 = blockIdx.z * (blockDim.x * QPT) + tid * QPT;
    if (q0 >= n_on) return;
    if (EMIT && q0 < 480 && pbase + PC <= 720)
        mainloopA<PC, QPT, true >(M, hd, pout, ch, b, q0);
    else
        mainloopA<PC, QPT, false>(M, hd, pout, ch, b, q0);
}

// ---------------------------------------------------------------------------
// F3 (fp16 pack path): prologue = iteration-2 update for its 30-row window
// (NCHP=8 chunks of PC=120 from F2, NACTP=6, C0->C1), QLO=480.
// mainloop: partials(3)[24 chunks of PC=30][b][q<480] from g_pack.
// ---------------------------------------------------------------------------
__global__ void phaseF3h(const float* __restrict__ hin, float* __restrict__ hout,
                         const float* __restrict__ Cin, float* __restrict__ Cout,
                         const float* __restrict__ pin, float* __restrict__ pout,
                         float* __restrict__ outF)
{
#if __CUDA_ARCH__ >= 900
    cudaGridDependencySynchronize();
#endif
    const int ch = blockIdx.x, b = blockIdx.y, tid = threadIdx.x;
    const int PC = 30;
    __shared__ float2 hd[30];

    if (tid < PC) {
        const int q  = ch * PC + tid;
        const int gi = b * PP + q;
        float h = hin[gi];
        float sa = 0.0f, sf = 0.0f;
        const float* pp = pin + (size_t)b * PP + q;
        #pragma unroll
        for (int s = 0; s < 8; ++s) {
            float v = pp[(size_t)s * NPB];
            if (s < 6) sa += v; else sf += v;
        }
        float c = Cin[gi];
        float hnew = f_p(h * (0.8f + sa + sf + c));
        hd[tid] = make_float2(hnew, hnew);
        if (q >= 480) {
            outF[gi] = hnew;
        } else {
            hout[gi] = hnew;
            Cout[gi] = c + sf;
        }
    }
    __syncthreads();

    const int q0 = tid * 8;
    if (q0 >= 480) return;
    const int qblk = q0 / 240, qin = q0 % 240;
    const char* pk = (const char*)(g_pack
        + (((size_t)b * 2 + qblk) * 720 + ch * PC) * 240 + qin);

    unsigned long long acc0 = 0, acc1 = 0, acc2 = 0, acc3 = 0;
    #pragma unroll
    for (int p = 0; p < PC; ++p) {
        unsigned long long hp = *reinterpret_cast<const unsigned long long*>(&hd[p]);
        U64x2 m = ldg_cs_128(pk + (size_t)p * 480);
        FMA2(acc0, h2_to_f2((unsigned)m.a), hp);
        FMA2(acc1, h2_to_f2((unsigned)(m.a >> 32)), hp);
        FMA2(acc2, h2_to_f2((unsigned)m.b), hp);
        FMA2(acc3, h2_to_f2((unsigned)(m.b >> 32)), hp);
    }
    unsigned long long* out = reinterpret_cast<unsigned long long*>(
        pout + ((size_t)ch * BB + b) * PP + q0);
    out[0] = acc0; out[1] = acc1; out[2] = acc2; out[3] = acc3;
}

// ---------------------------------------------------------------------------
// F4 (fp16 pack path): prologue = iteration-3 update for its 15-row window
// (NCHP=24 chunks of PC=30 from F3, NACTP=16, C1->C0), QLO=240.
// mainloop: partials(4)[32 chunks of PC=15][b][q<240] from g_pack qblk 0.
// ---------------------------------------------------------------------------
__global__ void phaseF4h(const float* __restrict__ hin, float* __restrict__ hout,
                         const float* __restrict__ Cin, float* __restrict__ Cout,
                         const float* __restrict__ pin, float* __restrict__ pout,
                         float* __restrict__ outF)
{
#if __CUDA_ARCH__ >= 900
    cudaGridDependencySynchronize();
#endif
    const int ch = blockIdx.x, b = blockIdx.y, tid = threadIdx.x;
    const int PC = 15;
    __shared__ float2 hd[15];

    if (tid < PC) {
        const int q  = ch * PC + tid;
        const int gi = b * PP + q;
        float h = hin[gi];
        float sa = 0.0f, sf = 0.0f;
        const float* pp = pin + (size_t)b * PP + q;
        #pragma unroll
        for (int s = 0; s < 24; ++s) {
            float v = pp[(size_t)s * NPB];
            if (s < 16) sa += v; else sf += v;
        }
        float c = Cin[gi];
        float hnew = f_p(h * (0.8f + sa + sf + c));
        hd[tid] = make_float2(hnew, hnew);
        if (q >= 240) {
            outF[gi] = hnew;
        } else {
            hout[gi] = hnew;
            Cout[gi] = c + sf;
        }
    }
    __syncthreads();

    const int q0 = tid * 4;
    if (q0 >= 240) return;
    const char* pk = (const char*)(g_pack
        + ((size_t)b * 2 * 720 + ch * PC) * 240 + q0);

    unsigned long long acc0 = 0, acc1 = 0;
    #pragma unroll
    for (int p = 0; p < PC; ++p) {
        unsigned long long hp = *reinterpret_cast<const unsigned long long*>(&hd[p]);
        unsigned long long m = ldg_cs_64(pk + (size_t)p * 480);
        FMA2(acc0, h2_to_f2((unsigned)m), hp);
        FMA2(acc1, h2_to_f2((unsigned)(m >> 32)), hp);
    }
    unsigned long long* out = reinterpret_cast<unsigned long long*>(
        pout + ((size_t)ch * BB + b) * PP + q0);
    out[0] = acc0; out[1] = acc1;
}

// ---------------------------------------------------------------------------
// final update (q<240 only; frozen slices already written by F prologues):
// out[q<240] = f_p(hB*(0.8 + C0 + sum of 32 chunks of pA))
// ---------------------------------------------------------------------------
__global__ void phaseBfinal(float4* __restrict__ out)
{
#if __CUDA_ARCH__ >= 900
    cudaGridDependencySynchronize();
#endif
    int i4 = blockIdx.x * blockDim.x + threadIdx.x;   // over BB*60 groups
    if (i4 >= BB * 60) return;
    int b = i4 / 60, r = i4 % 60;
    int q = r * 4;
    int gi4 = (b * PP + q) / 4;

    float4 s = make_float4(0.f, 0.f, 0.f, 0.f);
    const float* pp = g_pA + (size_t)b * PP + q;
    #pragma unroll
    for (int sI = 0; sI < 32; ++sI) {
        float4 v = *reinterpret_cast<const float4*>(pp + (size_t)sI * NPB);
        s.x += v.x; s.y += v.y; s.z += v.z; s.w += v.w;
    }

    float4 h = reinterpret_cast<const float4*>(g_hB)[gi4];
    float4 c = reinterpret_cast<const float4*>(g_C0)[gi4];
    float4 o;
    o.x = f_p(h.x * (0.8f + s.x + c.x));
    o.y = f_p(h.y * (0.8f + s.y + c.y));
    o.z = f_p(h.z * (0.8f + s.z + c.z));
    o.w = f_p(h.w * (0.8f + s.w + c.w));
    out[gi4] = o;
}

// ---------------------------------------------------------------------------
// helper: launch with programmatic stream serialization (PDL)
// ---------------------------------------------------------------------------
template<typename K, typename... Args>
static void launch_pdl(dim3 grid, dim3 block, K kernel, Args... args)
{
    cudaLaunchConfig_t cfg = {};
    cfg.gridDim  = grid;
    cfg.blockDim = block;
    cudaLaunchAttribute attr[1];
    attr[0].id = cudaLaunchAttributeProgrammaticStreamSerialization;
    attr[0].val.programmaticStreamSerializationAllowed = 1;
    cfg.attrs = attr;
    cfg.numAttrs = 1;
    cudaLaunchKernelEx(&cfg, kernel, args...);
}

// ---------------------------------------------------------------------------
extern "C" void kernel_launch(void* const* d_in, const int* in_sizes, int n_in,
                              void* d_out, int out_size)
{
    const float* query = (const float*)d_in[0];
    const float* M     = (const float*)d_in[1];
    float*       out   = (float*)d_out;

    float *hA, *hB, *C0, *C1, *pA, *pB;
    cudaGetSymbolAddress((void**)&hA, g_hA);
    cudaGetSymbolAddress((void**)&hB, g_hB);
    cudaGetSymbolAddress((void**)&C0, g_C0);
    cudaGetSymbolAddress((void**)&C1, g_C1);
    cudaGetSymbolAddress((void**)&pA, g_pA);
    cudaGetSymbolAddress((void**)&pB, g_pB);

    // Plan:
    //  launch : pc  chunks p-range q-range prologue              h        C       partials
    //  A0     : 120 10     <1200   <1200   -                     query    -       ->pA
    //  F1     : 120 10     <1200   <960    (10,10) out[960,1200) q->hA    -       pA->pB
    //  F2     : 120  8     <960    <720    (10,8) wC0 out[720,960) hA->hB ->C0    pB->pA
    //           + emits fp16 pack of (p<720, q<480)
    //  F3h    :  30 24     <720    <480    ( 8,6) rC0 wC1 out[480,720) hB->hA C0->C1 pA->pB
    //  F4h    :  15 32     <480    <240    (24,16) rC1 wC0 out[240,480) hA->hB C1->C0 pB->pA
    //  Bfinal : out[q<240] from hB, C0, pA(32 chunks)

    phaseA0<120><<<dim3(10, BB, 3), 128>>>(M, query);

    launch_pdl(dim3(10, BB, 2), dim3(128),
               phaseF<120, 4, 10, 10, false, false, false, true,  960, false>,
               M, query, hA, (const float*)C0, C1, (const float*)pA, pB, out, 960);

    launch_pdl(dim3( 8, BB, 2), dim3(128),
               phaseF<120, 4, 10,  8, false, true,  true,  false, 720, true >,
               M, (const float*)hA, hB, (const float*)C1, C0,
               (const float*)pB, pA, out, 720);

    launch_pdl(dim3(24, BB, 1), dim3(64), phaseF3h,
               (const float*)hB, hA, (const float*)C0, C1,
               (const float*)pA, pB, out);

    launch_pdl(dim3(32, BB, 1), dim3(64), phaseF4h,
               (const float*)hA, hB, (const float*)C1, C0,
               (const float*)pB, pA, out);

    launch_pdl(dim3(30), dim3(256), phaseBfinal, (float4*)out);
}

// round 14
// speedup vs baseline: 1.1595x; 1.1595x over previous
#include <cuda_runtime.h>
#include <cuda_fp16.h>
#include <cstdint>

#define BB 128          // batch
#define PP 1200         // feature dim
#define NPB (BB * PP)   // 153600
#define MAXCH 16        // max p-chunks per iteration
#define QW 960          // pack row width (halves)

// Static scratch (ping-pong everything to avoid same-launch read/write races)
__device__ float g_hA[NPB];               // h state buffer A
__device__ float g_hB[NPB];               // h state buffer B
__device__ float g_C0[NPB];               // frozen-contribution cache buffers
__device__ float g_C1[NPB];
__device__ float g_pA[MAXCH * NPB];       // partial sums ping
__device__ float g_pB[MAXCH * NPB];       // partial sums pong
// fp16 pack of M[b, p<1200, q<960], emitted by A0, read by F1..F4 (295 MB)
__device__ __align__(16) __half g_pack[(size_t)BB * PP * QW];

__device__ __forceinline__ float f_p(float x) {
    float t = fminf(fmaxf(x, -1.0f), 1.0f);
    return t > 0.0f ? t : 0.01f * t;
}

// pure (non-volatile, no memory clobber) streaming loads: compiler may hoist
// and batch these freely, including across __stcs stores.
struct U64x2 { unsigned long long a, b; };
__device__ __forceinline__ U64x2 ldg_cs_128(const void* p) {
    U64x2 r;
    asm("ld.global.cs.v2.u64 {%0,%1}, [%2];" : "=l"(r.a), "=l"(r.b) : "l"(p));
    return r;
}
__device__ __forceinline__ unsigned long long ldg_cs_64(const void* p) {
    unsigned long long r;
    asm("ld.global.cs.u64 %0, [%1];" : "=l"(r) : "l"(p));
    return r;
}

// Packed dual-fp32 FMA: acc = m * hp + acc   (Blackwell f32x2 pipe)
#define FMA2(acc, m, hp) \
    asm("fma.rn.f32x2 %0, %1, %2, %0;" : "+l"(acc) : "l"(m), "l"(hp))

// fp16x2 (as uint32) -> packed f32x2 (as ull)
__device__ __forceinline__ unsigned long long h2_to_f2(unsigned int h2) {
    __half2 hh = *reinterpret_cast<__half2*>(&h2);
    float2 f = __half22float2(hh);
    return *reinterpret_cast<unsigned long long*>(&f);
}

// ---------------------------------------------------------------------------
// A0: h0 = f_p(query); partials(0) -> pA over all q<1200; while the fp32 M
// values are in registers, emit the fp16 pack for q<960 via __stcs (compiler-
// visible store -> no load-hoisting barrier).
// ---------------------------------------------------------------------------
template<int PC>
__global__ void phaseA0(const float* __restrict__ M, const float* __restrict__ query)
{
    const int ch = blockIdx.x, b = blockIdx.y, tid = threadIdx.x;
    const int pbase = ch * PC;
    __shared__ float2 hd[PC];
    if (tid < PC) {
        float v = f_p(query[b * PP + pbase + tid]);
        hd[tid] = make_float2(v, v);
    }
    __syncthreads();

    const int q0 = blockIdx.z * 512 + tid * 4;
    if (q0 >= PP) return;

    const char* base = (const char*)(M + (size_t)b * PP * PP
                                       + (size_t)pbase * PP + q0);
    const bool emit = (q0 < QW);
    __half* pk = g_pack + ((size_t)(b * PP + pbase)) * QW + q0;

    unsigned long long acc0 = 0, acc1 = 0;

    #pragma unroll 8
    for (int p = 0; p < PC; ++p) {
        unsigned long long hp = *reinterpret_cast<const unsigned long long*>(&hd[p]);
        U64x2 m = ldg_cs_128(base + (size_t)p * (PP * 4));
        FMA2(acc0, m.a, hp);
        FMA2(acc1, m.b, hp);
        if (emit) {
            float2 lo = *reinterpret_cast<float2*>(&m.a);
            float2 hi = *reinterpret_cast<float2*>(&m.b);
            __half2 hlo = __float22half2_rn(lo);
            __half2 hhi = __float22half2_rn(hi);
            unsigned long long v =
                (unsigned long long)(*reinterpret_cast<unsigned*>(&hlo)) |
                ((unsigned long long)(*reinterpret_cast<unsigned*>(&hhi)) << 32);
            __stcs(reinterpret_cast<unsigned long long*>(pk + (size_t)p * QW), v);
        }
    }

    unsigned long long* out = reinterpret_cast<unsigned long long*>(
        g_pA + ((size_t)ch * BB + b) * PP + q0);
    out[0] = acc0;
    out[1] = acc1;
}

// ---------------------------------------------------------------------------
// fused fp16-path kernel F_t:
//   prologue (tid<PC): h_t = f_p(h_{t-1}*(0.8 + C_in + sum partials_in));
//     q>=QLO slice of the window goes straight to d_out (just frozen);
//     else persist h and fold frozen chunks into C_out.
//   mainloop: partials_t[ch][b][q<NON] from the fp16 pack.
//   HQ = halves per thread (8 -> LDG.128/p, 4 -> LDG.64/p).
// ---------------------------------------------------------------------------
template<int PC, int HQ, int NCHP, int NACTP,
         bool READC, bool WRITEC, bool FIRSTW, bool IT0P, int QLO, int NON>
__global__ void phaseFh(const float* __restrict__ hin, float* __restrict__ hout,
                        const float* __restrict__ Cin, float* __restrict__ Cout,
                        const float* __restrict__ pin, float* __restrict__ pout,
                        float* __restrict__ outF)
{
#if __CUDA_ARCH__ >= 900
    cudaGridDependencySynchronize();
#endif
    const int ch = blockIdx.x, b = blockIdx.y, tid = threadIdx.x;
    const int pbase = ch * PC;
    __shared__ float2 hd[PC];

    if (tid < PC) {
        const int q  = pbase + tid;
        const int gi = b * PP + q;
        float h = hin[gi];
        if (IT0P) h = f_p(h);

        float sa = 0.0f, sf = 0.0f;
        const float* pp = pin + (size_t)b * PP + q;
        #pragma unroll
        for (int s = 0; s < NCHP; ++s) {
            float v = pp[(size_t)s * NPB];
            if (s < NACTP) sa += v; else sf += v;
        }
        float c = READC ? Cin[gi] : 0.0f;
        float hnew = f_p(h * (0.8f + sa + sf + c));
        hd[tid] = make_float2(hnew, hnew);

        if (q >= QLO) {
            outF[gi] = hnew;                 // just-frozen final slice
        } else {
            hout[gi] = hnew;
            if (WRITEC) Cout[gi] = FIRSTW ? sf : (c + sf);
        }
    }
    __syncthreads();

    const int q0 = tid * HQ;
    if (q0 >= NON) return;

    const char* pk = (const char*)(g_pack + ((size_t)(b * PP + pbase)) * QW + q0);

    if (HQ == 8) {
        unsigned long long acc0 = 0, acc1 = 0, acc2 = 0, acc3 = 0;
        #pragma unroll 8
        for (int p = 0; p < PC; ++p) {
            unsigned long long hp = *reinterpret_cast<const unsigned long long*>(&hd[p]);
            U64x2 m = ldg_cs_128(pk + (size_t)p * (QW * 2));
            FMA2(acc0, h2_to_f2((unsigned)m.a), hp);
            FMA2(acc1, h2_to_f2((unsigned)(m.a >> 32)), hp);
            FMA2(acc2, h2_to_f2((unsigned)m.b), hp);
            FMA2(acc3, h2_to_f2((unsigned)(m.b >> 32)), hp);
        }
        unsigned long long* out = reinterpret_cast<unsigned long long*>(
            pout + ((size_t)ch * BB + b) * PP + q0);
        out[0] = acc0; out[1] = acc1; out[2] = acc2; out[3] = acc3;
    } else {
        unsigned long long acc0 = 0, acc1 = 0;
        #pragma unroll 8
        for (int p = 0; p < PC; ++p) {
            unsigned long long hp = *reinterpret_cast<const unsigned long long*>(&hd[p]);
            unsigned long long m = ldg_cs_64(pk + (size_t)p * (QW * 2));
            FMA2(acc0, h2_to_f2((unsigned)m), hp);
            FMA2(acc1, h2_to_f2((unsigned)(m >> 32)), hp);
        }
        unsigned long long* out = reinterpret_cast<unsigned long long*>(
            pout + ((size_t)ch * BB + b) * PP + q0);
        out[0] = acc0; out[1] = acc1;
    }
}

// ---------------------------------------------------------------------------
// final update (q<240 only; frozen slices already written by F prologues):
// out[q<240] = f_p(hB*(0.8 + C0 + sum of 16 chunks of pA))
// ---------------------------------------------------------------------------
__global__ void phaseBfinal(float4* __restrict__ out)
{
#if __CUDA_ARCH__ >= 900
    cudaGridDependencySynchronize();
#endif
    int i4 = blockIdx.x * blockDim.x + threadIdx.x;   // over BB*60 groups
    if (i4 >= BB * 60) return;
    int b = i4 / 60, r = i4 % 60;
    int q = r * 4;
    int gi4 = (b * PP + q) / 4;

    float4 s = make_float4(0.f, 0.f, 0.f, 0.f);
    const float* pp = g_pA + (size_t)b * PP + q;
    #pragma unroll
    for (int sI = 0; sI < 16; ++sI) {
        float4 v = *reinterpret_cast<const float4*>(pp + (size_t)sI * NPB);
        s.x += v.x; s.y += v.y; s.z += v.z; s.w += v.w;
    }

    float4 h = reinterpret_cast<const float4*>(g_hB)[gi4];
    float4 c = reinterpret_cast<const float4*>(g_C0)[gi4];
    float4 o;
    o.x = f_p(h.x * (0.8f + s.x + c.x));
    o.y = f_p(h.y * (0.8f + s.y + c.y));
    o.z = f_p(h.z * (0.8f + s.z + c.z));
    o.w = f_p(h.w * (0.8f + s.w + c.w));
    out[gi4] = o;
}

// ---------------------------------------------------------------------------
// helper: launch with programmatic stream serialization (PDL)
// ---------------------------------------------------------------------------
template<typename K, typename... Args>
static void launch_pdl(dim3 grid, dim3 block, K kernel, Args... args)
{
    cudaLaunchConfig_t cfg = {};
    cfg.gridDim  = grid;
    cfg.blockDim = block;
    cudaLaunchAttribute attr[1];
    attr[0].id = cudaLaunchAttributeProgrammaticStreamSerialization;
    attr[0].val.programmaticStreamSerializationAllowed = 1;
    cfg.attrs = attr;
    cfg.numAttrs = 1;
    cudaLaunchKernelEx(&cfg, kernel, args...);
}

// ---------------------------------------------------------------------------
extern "C" void kernel_launch(void* const* d_in, const int* in_sizes, int n_in,
                              void* d_out, int out_size)
{
    const float* query = (const float*)d_in[0];
    const float* M     = (const float*)d_in[1];
    float*       out   = (float*)d_out;

    float *hA, *hB, *C0, *C1, *pA, *pB;
    cudaGetSymbolAddress((void**)&hA, g_hA);
    cudaGetSymbolAddress((void**)&hB, g_hB);
    cudaGetSymbolAddress((void**)&C0, g_C0);
    cudaGetSymbolAddress((void**)&C1, g_C1);
    cudaGetSymbolAddress((void**)&pA, g_pA);
    cudaGetSymbolAddress((void**)&pB, g_pB);

    // Plan:
    //  launch : pc chunks hq  p-range q-range prologue(NCHP,NACTP)          h        C       partials
    //  A0     : 120 10     -  <1200   <1200   -                             query    -       ->pA
    //           + emits fp16 pack of (p<1200, q<960)
    //  F1     : 120 10     8  <1200   <960    (10,10) noC IT0 out[960,1200) q->hA    -       pA->pB
    //  F2     : 120  8     4  <960    <720    (10, 8) wC0 first out[720,960) hA->hB  ->C0    pB->pA
    //  F3     :  60 12     4  <720    <480    ( 8, 6) rC0 wC1 out[480,720)  hB->hA   C0->C1  pA->pB
    //  F4     :  30 16     4  <480    <240    (12, 8) rC1 wC0 out[240,480)  hA->hB   C1->C0  pB->pA
    //  Bfinal : out[q<240] from hB, C0, pA(16 chunks)

    phaseA0<120><<<dim3(10, BB, 3), 128>>>(M, query);

    launch_pdl(dim3(10, BB, 1), dim3(128),
               phaseFh<120, 8, 10, 10, false, false, false, true,  960, 960>,
               query, hA, (const float*)C0, C1, (const float*)pA, pB, out);

    launch_pdl(dim3( 8, BB, 1), dim3(192),
               phaseFh<120, 4, 10,  8, false, true,  true,  false, 720, 720>,
               (const float*)hA, hB, (const float*)C1, C0,
               (const float*)pB, pA, out);

    launch_pdl(dim3(12, BB, 1), dim3(128),
               phaseFh< 60, 4,  8,  6, true,  true,  false, false, 480, 480>,
               (const float*)hB, hA, (const float*)C0, C1,
               (const float*)pA, pB, out);

    launch_pdl(dim3(16, BB, 1), dim3(64),
               phaseFh< 30, 4, 12,  8, true,  true,  false, false, 240, 240>,
               (const float*)hA, hB, (const float*)C1, C0,
               (const float*)pB, pA, out);

    launch_pdl(dim3(30), dim3(256), phaseBfinal, (float4*)out);
}

// round 17
// speedup vs baseline: 1.1666x; 1.0061x over previous
#include <cuda_runtime.h>
#include <cuda_fp16.h>
#include <cstdint>

#define BB 128          // batch
#define PP 1200         // feature dim
#define NPB (BB * PP)   // 153600
#define MAXCH 16        // max p-chunks per iteration
#define QB 240          // q-block width (halves)

// Static scratch (ping-pong everything to avoid same-launch read/write races)
__device__ float g_hA[NPB];               // h state buffer A
__device__ float g_hB[NPB];               // h state buffer B
__device__ float g_C0[NPB];               // frozen-contribution cache buffers
__device__ float g_C1[NPB];
__device__ float g_pA[MAXCH * NPB];       // partial sums ping
__device__ float g_pB[MAXCH * NPB];       // partial sums pong
// fp16 pack of M[b, p<1200, q<960] in q-block-major layout
// [qblk(4)][b][p(1200)][qin(240)] -- every later reader touches a dense
// contiguous prefix (full DRAM duty). Emitted by A0. 295 MB.
__device__ __align__(16) __half g_pack[(size_t)4 * BB * PP * QB];

__device__ __forceinline__ float f_p(float x) {
    float t = fminf(fmaxf(x, -1.0f), 1.0f);
    return t > 0.0f ? t : 0.01f * t;
}

// pure (non-volatile, no memory clobber) streaming loads: compiler may hoist
// and batch these freely, including across __stcs stores.
struct U64x2 { unsigned long long a, b; };
__device__ __forceinline__ U64x2 ldg_cs_128(const void* p) {
    U64x2 r;
    asm("ld.global.cs.v2.u64 {%0,%1}, [%2];" : "=l"(r.a), "=l"(r.b) : "l"(p));
    return r;
}
__device__ __forceinline__ unsigned long long ldg_cs_64(const void* p) {
    unsigned long long r;
    asm("ld.global.cs.u64 %0, [%1];" : "=l"(r) : "l"(p));
    return r;
}

// Packed dual-fp32 FMA: acc = m * hp + acc   (Blackwell f32x2 pipe)
#define FMA2(acc, m, hp) \
    asm("fma.rn.f32x2 %0, %1, %2, %0;" : "+l"(acc) : "l"(m), "l"(hp))

// fp16x2 (as uint32) -> packed f32x2 (as ull)
__device__ __forceinline__ unsigned long long h2_to_f2(unsigned int h2) {
    __half2 hh = *reinterpret_cast<__half2*>(&h2);
    float2 f = __half22float2(hh);
    return *reinterpret_cast<unsigned long long*>(&f);
}

// ---------------------------------------------------------------------------
// A0: h0 = f_p(query); partials(0) -> pA over all q<1200; while the fp32 M
// values are in registers, emit the fp16 pack (q<960) into q-block-major
// layout via __stcs (compiler-visible store -> loads stay hoistable).
// ---------------------------------------------------------------------------
template<int PC>
__global__ void phaseA0(const float* __restrict__ M, const float* __restrict__ query)
{
    const int ch = blockIdx.x, b = blockIdx.y, tid = threadIdx.x;
    const int pbase = ch * PC;
    __shared__ float2 hd[PC];
    if (tid < PC) {
        float v = f_p(query[b * PP + pbase + tid]);
        hd[tid] = make_float2(v, v);
    }
    __syncthreads();

    const int q0 = blockIdx.z * 512 + tid * 4;
    if (q0 >= PP) return;

    const char* base = (const char*)(M + (size_t)b * PP * PP
                                       + (size_t)pbase * PP + q0);
    const bool emit = (q0 < 960);
    const int qblk = q0 / QB, qin = q0 % QB;   // 4-float group never crosses QB
    __half* pk = g_pack + (((size_t)qblk * BB + b) * PP + pbase) * QB + qin;

    unsigned long long acc0 = 0, acc1 = 0;

    #pragma unroll 8
    for (int p = 0; p < PC; ++p) {
        unsigned long long hp = *reinterpret_cast<const unsigned long long*>(&hd[p]);
        U64x2 m = ldg_cs_128(base + (size_t)p * (PP * 4));
        FMA2(acc0, m.a, hp);
        FMA2(acc1, m.b, hp);
        if (emit) {
            float2 lo = *reinterpret_cast<float2*>(&m.a);
            float2 hi = *reinterpret_cast<float2*>(&m.b);
            __half2 hlo = __float22half2_rn(lo);
            __half2 hhi = __float22half2_rn(hi);
            unsigned long long v =
                (unsigned long long)(*reinterpret_cast<unsigned*>(&hlo)) |
                ((unsigned long long)(*reinterpret_cast<unsigned*>(&hhi)) << 32);
            __stcs(reinterpret_cast<unsigned long long*>(pk + (size_t)p * QB), v);
        }
    }

    unsigned long long* out = reinterpret_cast<unsigned long long*>(
        g_pA + ((size_t)ch * BB + b) * PP + q0);
    out[0] = acc0;
    out[1] = acc1;
}

// ---------------------------------------------------------------------------
// fused fp16-path kernel F_t:
//   prologue (tid<PC): h_t = f_p(h_{t-1}*(0.8 + C_in + sum partials_in));
//     q>=QLO slice of the window goes straight to d_out (just frozen);
//     else persist h and fold frozen chunks into C_out.
//   mainloop: partials_t[ch][b][q<NON] from the q-block-major fp16 pack.
//   HQ = halves per thread (8 -> LDG.128/p, 4 -> LDG.64/p).
// ---------------------------------------------------------------------------
template<int PC, int HQ, int NCHP, int NACTP,
         bool READC, bool WRITEC, bool FIRSTW, bool IT0P, int QLO, int NON>
__global__ void phaseFh(const float* __restrict__ hin, float* __restrict__ hout,
                        const float* __restrict__ Cin, float* __restrict__ Cout,
                        const float* __restrict__ pin, float* __restrict__ pout,
                        float* __restrict__ outF)
{
#if __CUDA_ARCH__ >= 900
    cudaGridDependencySynchronize();
#endif
    const int ch = blockIdx.x, b = blockIdx.y, tid = threadIdx.x;
    const int pbase = ch * PC;
    __shared__ float2 hd[PC];

    if (tid < PC) {
        const int q  = pbase + tid;
        const int gi = b * PP + q;
        float h = hin[gi];
        if (IT0P) h = f_p(h);

        float sa = 0.0f, sf = 0.0f;
        const float* pp = pin + (size_t)b * PP + q;
        #pragma unroll
        for (int s = 0; s < NCHP; ++s) {
            float v = pp[(size_t)s * NPB];
            if (s < NACTP) sa += v; else sf += v;
        }
        float c = READC ? Cin[gi] : 0.0f;
        float hnew = f_p(h * (0.8f + sa + sf + c));
        hd[tid] = make_float2(hnew, hnew);

        if (q >= QLO) {
            outF[gi] = hnew;                 // just-frozen final slice
        } else {
            hout[gi] = hnew;
            if (WRITEC) Cout[gi] = FIRSTW ? sf : (c + sf);
        }
    }
    __syncthreads();

    const int q0 = tid * HQ;                 // HQ | QB, so no group crosses QB
    if (q0 >= NON) return;
    const int qblk = q0 / QB, qin = q0 % QB;

    const char* pk = (const char*)(g_pack
        + (((size_t)qblk * BB + b) * PP + pbase) * QB + qin);

    if (HQ == 8) {
        unsigned long long acc0 = 0, acc1 = 0, acc2 = 0, acc3 = 0;
        #pragma unroll 8
        for (int p = 0; p < PC; ++p) {
            unsigned long long hp = *reinterpret_cast<const unsigned long long*>(&hd[p]);
            U64x2 m = ldg_cs_128(pk + (size_t)p * (QB * 2));
            FMA2(acc0, h2_to_f2((unsigned)m.a), hp);
            FMA2(acc1, h2_to_f2((unsigned)(m.a >> 32)), hp);
            FMA2(acc2, h2_to_f2((unsigned)m.b), hp);
            FMA2(acc3, h2_to_f2((unsigned)(m.b >> 32)), hp);
        }
        unsigned long long* out = reinterpret_cast<unsigned long long*>(
            pout + ((size_t)ch * BB + b) * PP + q0);
        out[0] = acc0; out[1] = acc1; out[2] = acc2; out[3] = acc3;
    } else {
        unsigned long long acc0 = 0, acc1 = 0;
        #pragma unroll 8
        for (int p = 0; p < PC; ++p) {
            unsigned long long hp = *reinterpret_cast<const unsigned long long*>(&hd[p]);
            unsigned long long m = ldg_cs_64(pk + (size_t)p * (QB * 2));
            FMA2(acc0, h2_to_f2((unsigned)m), hp);
            FMA2(acc1, h2_to_f2((unsigned)(m >> 32)), hp);
        }
        unsigned long long* out = reinterpret_cast<unsigned long long*>(
            pout + ((size_t)ch * BB + b) * PP + q0);
        out[0] = acc0; out[1] = acc1;
    }
}

// ---------------------------------------------------------------------------
// final update (q<240 only; frozen slices already written by F prologues):
// out[q<240] = f_p(hB*(0.8 + C0 + sum of 16 chunks of pA))
// ---------------------------------------------------------------------------
__global__ void phaseBfinal(float4* __restrict__ out)
{
#if __CUDA_ARCH__ >= 900
    cudaGridDependencySynchronize();
#endif
    int i4 = blockIdx.x * blockDim.x + threadIdx.x;   // over BB*60 groups
    if (i4 >= BB * 60) return;
    int b = i4 / 60, r = i4 % 60;
    int q = r * 4;
    int gi4 = (b * PP + q) / 4;

    float4 s = make_float4(0.f, 0.f, 0.f, 0.f);
    const float* pp = g_pA + (size_t)b * PP + q;
    #pragma unroll
    for (int sI = 0; sI < 16; ++sI) {
        float4 v = *reinterpret_cast<const float4*>(pp + (size_t)sI * NPB);
        s.x += v.x; s.y += v.y; s.z += v.z; s.w += v.w;
    }

    float4 h = reinterpret_cast<const float4*>(g_hB)[gi4];
    float4 c = reinterpret_cast<const float4*>(g_C0)[gi4];
    float4 o;
    o.x = f_p(h.x * (0.8f + s.x + c.x));
    o.y = f_p(h.y * (0.8f + s.y + c.y));
    o.z = f_p(h.z * (0.8f + s.z + c.z));
    o.w = f_p(h.w * (0.8f + s.w + c.w));
    out[gi4] = o;
}

// ---------------------------------------------------------------------------
// helper: launch with programmatic stream serialization (PDL)
// ---------------------------------------------------------------------------
template<typename K, typename... Args>
static void launch_pdl(dim3 grid, dim3 block, K kernel, Args... args)
{
    cudaLaunchConfig_t cfg = {};
    cfg.gridDim  = grid;
    cfg.blockDim = block;
    cudaLaunchAttribute attr[1];
    attr[0].id = cudaLaunchAttributeProgrammaticStreamSerialization;
    attr[0].val.programmaticStreamSerializationAllowed = 1;
    cfg.attrs = attr;
    cfg.numAttrs = 1;
    cudaLaunchKernelEx(&cfg, kernel, args...);
}

// ---------------------------------------------------------------------------
extern "C" void kernel_launch(void* const* d_in, const int* in_sizes, int n_in,
                              void* d_out, int out_size)
{
    const float* query = (const float*)d_in[0];
    const float* M     = (const float*)d_in[1];
    float*       out   = (float*)d_out;

    float *hA, *hB, *C0, *C1, *pA, *pB;
    cudaGetSymbolAddress((void**)&hA, g_hA);
    cudaGetSymbolAddress((void**)&hB, g_hB);
    cudaGetSymbolAddress((void**)&C0, g_C0);
    cudaGetSymbolAddress((void**)&C1, g_C1);
    cudaGetSymbolAddress((void**)&pA, g_pA);
    cudaGetSymbolAddress((void**)&pB, g_pB);

    // Plan:
    //  launch : pc chunks hq  p-range q-range prologue(NCHP,NACTP)          h        C       partials
    //  A0     : 120 10     -  <1200   <1200   -                             query    -       ->pA
    //           + emits q-block-major fp16 pack of (p<1200, q<960)
    //  F1     : 120 10     8  <1200   <960    (10,10) noC IT0 out[960,1200) q->hA    -       pA->pB
    //  F2     : 120  8     4  <960    <720    (10, 8) wC0 first out[720,960) hA->hB  ->C0    pB->pA
    //  F3     :  60 12     4  <720    <480    ( 8, 6) rC0 wC1 out[480,720)  hB->hA   C0->C1  pA->pB
    //  F4     :  30 16     4  <480    <240    (12, 8) rC1 wC0 out[240,480)  hA->hB   C1->C0  pB->pA
    //  Bfinal : out[q<240] from hB, C0, pA(16 chunks)

    phaseA0<120><<<dim3(10, BB, 3), 128>>>(M, query);

    launch_pdl(dim3(10, BB, 1), dim3(128),
               phaseFh<120, 8, 10, 10, false, false, false, true,  960, 960>,
               query, hA, (const float*)C0, C1, (const float*)pA, pB, out);

    launch_pdl(dim3( 8, BB, 1), dim3(192),
               phaseFh<120, 4, 10,  8, false, true,  true,  false, 720, 720>,
               (const float*)hA, hB, (const float*)C1, C0,
               (const float*)pB, pA, out);

    launch_pdl(dim3(12, BB, 1), dim3(128),
               phaseFh< 60, 4,  8,  6, true,  true,  false, false, 480, 480>,
               (const float*)hB, hA, (const float*)C0, C1,
               (const float*)pA, pB, out);

    launch_pdl(dim3(16, BB, 1), dim3(64),
               phaseFh< 30, 4, 12,  8, true,  true,  false, false, 240, 240>,
               (const float*)hA, hB, (const float*)C1, C0,
               (const float*)pB, pA, out);

    launch_pdl(dim3(30), dim3(256), phaseBfinal, (float4*)out);
}